// round 2
// baseline (speedup 1.0000x reference)
#include <cuda_runtime.h>
#include <cuda_fp16.h>
#include <cstdint>
#include <cstddef>

// Problem dims (fixed by the dataset)
#define KIN   4096
#define NROWS 8192
#define NOUT  4096
#define BASIS 8

// GEMM tiling
#define BM 128
#define BN 256
#define BK 64
#define STAGES 4
#define THREADS 512
#define NKT (KIN / BK)            // 64 k-iterations

#define A_BYTES (BM * BK * 2)     // 16384
#define B_BYTES (BN * BK * 2)     // 32768
#define STG_BYTES (A_BYTES + B_BYTES)        // 49152
#define SMEM_TOTAL (STAGES * STG_BYTES)      // 196608

// ---------------- scratch (device globals; no runtime allocation) ----------------
__device__ __half g_w[(size_t)NOUT  * KIN];   // fp16(w_approx), [out, in] K-contiguous
__device__ __half g_x[(size_t)NROWS * KIN];   // fp16(x),        [row, in] K-contiguous

// ---------------- PTX helpers ----------------
__device__ __forceinline__ uint32_t smem_u32(const void* p) {
    uint32_t a;
    asm("{ .reg .u64 t; cvta.to.shared.u64 t, %1; cvt.u32.u64 %0, t; }" : "=r"(a) : "l"(p));
    return a;
}

__device__ __forceinline__ void cp16(uint32_t dst, const void* src) {
    asm volatile("cp.async.cg.shared.global [%0], [%1], 16;" :: "r"(dst), "l"(src));
}
#define CP_COMMIT() asm volatile("cp.async.commit_group;" ::: "memory")

__device__ __forceinline__ void ldsm4(uint32_t (&r)[4], uint32_t addr) {
    asm volatile("ldmatrix.sync.aligned.m8n8.x4.shared.b16 {%0,%1,%2,%3}, [%4];"
                 : "=r"(r[0]), "=r"(r[1]), "=r"(r[2]), "=r"(r[3]) : "r"(addr));
}

__device__ __forceinline__ void mma16816(float (&c)[4], const uint32_t (&a)[4],
                                         uint32_t b0, uint32_t b1) {
    asm volatile(
        "mma.sync.aligned.m16n8k16.row.col.f32.f16.f16.f32 "
        "{%0,%1,%2,%3}, {%4,%5,%6,%7}, {%8,%9}, {%0,%1,%2,%3};"
        : "+f"(c[0]), "+f"(c[1]), "+f"(c[2]), "+f"(c[3])
        : "r"(a[0]), "r"(a[1]), "r"(a[2]), "r"(a[3]), "r"(b0), "r"(b1));
}

// ---------------- Kernel 1: binary decomposition -> fp16 W_approx ----------------
__global__ void __launch_bounds__(256) decompose_kernel(const float* __restrict__ W) {
    __shared__ float r[KIN];
    __shared__ float red[8];
    __shared__ float bc;
    const int row = blockIdx.x;
    const int t = threadIdx.x, wid = t >> 5, lid = t & 31;
    const float* wr = W + (size_t)row * KIN;

    float wl[16];
    float s = 0.f;
#pragma unroll
    for (int i = 0; i < 16; i++) { wl[i] = wr[t + 256 * i]; s += wl[i]; }
#pragma unroll
    for (int o = 16; o > 0; o >>= 1) s += __shfl_down_sync(0xffffffffu, s, o);
    if (lid == 0) red[wid] = s;
    __syncthreads();
    if (t == 0) {
        float tot = 0.f;
#pragma unroll
        for (int i = 0; i < 8; i++) tot += red[i];
        bc = tot * (1.f / KIN);
    }
    __syncthreads();
    const float offset = bc;
#pragma unroll
    for (int i = 0; i < 16; i++) r[t + 256 * i] = wl[i] - offset;
    __syncthreads();

    for (int b = 0; b < BASIS; b++) {
        float a = 0.f;
#pragma unroll
        for (int i = 0; i < 16; i++) a += fabsf(r[t + 256 * i]);
#pragma unroll
        for (int o = 16; o > 0; o >>= 1) a += __shfl_down_sync(0xffffffffu, a, o);
        if (lid == 0) red[wid] = a;
        __syncthreads();
        if (t == 0) {
            float tot = 0.f;
#pragma unroll
            for (int i = 0; i < 8; i++) tot += red[i];
            bc = tot * (1.f / KIN);
        }
        __syncthreads();
        const float c = bc;
#pragma unroll
        for (int i = 0; i < 16; i++) {
            float v = r[t + 256 * i];
            r[t + 256 * i] = v - (v >= 0.f ? c : -c);
        }
        __syncthreads();
    }
    // w_approx = w - r_final
    __half* wo = g_w + (size_t)row * KIN;
#pragma unroll
    for (int i = 0; i < 16; i++)
        wo[t + 256 * i] = __float2half_rn(wl[i] - r[t + 256 * i]);
}

// ---------------- Kernel 2: convert X to fp16 ----------------
__global__ void __launch_bounds__(256) cvtx_kernel(const float* __restrict__ x) {
    const size_t i = (size_t)blockIdx.x * 256 + threadIdx.x;  // grid sized exactly
    float4 v = reinterpret_cast<const float4*>(x)[i];
    __half2* x2 = reinterpret_cast<__half2*>(g_x);
    x2[2 * i + 0] = __halves2half2(__float2half_rn(v.x), __float2half_rn(v.y));
    x2[2 * i + 1] = __halves2half2(__float2half_rn(v.z), __float2half_rn(v.w));
}

// ---------------- Kernel 3: pipelined HMMA GEMM  out = X * W^T + bias ----------------
__global__ void __launch_bounds__(THREADS, 1) gemm_kernel(const float* __restrict__ bias,
                                                          float* __restrict__ out) {
    extern __shared__ char smem[];
    const uint32_t sb = smem_u32(smem);
    const int t = threadIdx.x, wid = t >> 5, lane = t & 31;
    const int bn0 = blockIdx.x * BN;   // N tile
    const int bm0 = blockIdx.y * BM;   // M tile

    const int warp_m = wid & 3;        // 4 M-warps -> 32 rows each
    const int warp_n = wid >> 2;       // 4 N-warps -> 64 cols each

    // per-thread cp.async coordinates (A: 2 chunks, B: 4 chunks of 16B per stage)
    // chunk c: row = c>>3, kc = c&7; swizzled dst = row*128 + ((kc ^ (row&7))<<4)
    const __half* a_gsrc = g_x + (size_t)bm0 * KIN;
    const __half* b_gsrc = g_w + (size_t)bn0 * KIN;

    int a_row[2], a_kc[2];
    uint32_t a_dst[2];
#pragma unroll
    for (int i = 0; i < 2; i++) {
        int c = t + THREADS * i;
        a_row[i] = c >> 3; a_kc[i] = c & 7;
        a_dst[i] = (uint32_t)(a_row[i] * 128 + ((a_kc[i] ^ (a_row[i] & 7)) << 4));
    }
    int b_row[4], b_kc[4];
    uint32_t b_dst[4];
#pragma unroll
    for (int i = 0; i < 4; i++) {
        int c = t + THREADS * i;
        b_row[i] = c >> 3; b_kc[i] = c & 7;
        b_dst[i] = (uint32_t)(b_row[i] * 128 + ((b_kc[i] ^ (b_row[i] & 7)) << 4)) + A_BYTES;
    }

    auto load_stage = [&](int kt, int s) {
        const uint32_t stb = sb + (uint32_t)s * STG_BYTES;
        const int k0 = kt * BK;
#pragma unroll
        for (int i = 0; i < 2; i++)
            cp16(stb + a_dst[i], a_gsrc + (size_t)a_row[i] * KIN + k0 + a_kc[i] * 8);
#pragma unroll
        for (int i = 0; i < 4; i++)
            cp16(stb + b_dst[i], b_gsrc + (size_t)b_row[i] * KIN + k0 + b_kc[i] * 8);
        CP_COMMIT();
    };

    // ldmatrix lane coordinates
    // A x4 tiles order: (m0,k0),(m8,k0),(m0,k8),(m8,k8)
    const int a_r  = warp_m * 32 + (lane & 7) + ((lane >> 3) & 1) * 8;  // + f*16
    const int a_hi = (lane >> 4) & 1;                                    // k-chunk +0/+1
    // B x4 tiles order: (n0,k0),(n0,k8),(n8,k0),(n8,k8)
    const int b_r  = warp_n * 64 + (lane & 7) + ((lane >> 4) & 1) * 8;   // + g*16
    const int b_hi = (lane >> 3) & 1;

    float acc[2][8][4];
#pragma unroll
    for (int f = 0; f < 2; f++)
#pragma unroll
        for (int g = 0; g < 8; g++)
#pragma unroll
            for (int q = 0; q < 4; q++) acc[f][g][q] = 0.f;

    // prologue: stages 0..STAGES-2
#pragma unroll
    for (int s = 0; s < STAGES - 1; s++) load_stage(s, s);

    for (int kt = 0; kt < NKT; ++kt) {
        asm volatile("cp.async.wait_group %0;" :: "n"(STAGES - 2) : "memory");
        __syncthreads();

        const int pf = kt + STAGES - 1;
        if (pf < NKT) load_stage(pf, pf % STAGES);
        else          CP_COMMIT();       // empty group keeps wait accounting correct

        const uint32_t stb = sb + (uint32_t)(kt % STAGES) * STG_BYTES;
#pragma unroll
        for (int ks = 0; ks < 4; ks++) {
            uint32_t a_frag[2][4];
#pragma unroll
            for (int f = 0; f < 2; f++) {
                uint32_t addr = stb + (uint32_t)((a_r + f * 16) * 128 +
                                (((ks * 2 + a_hi) ^ (a_r & 7)) << 4));
                ldsm4(a_frag[f], addr);
            }
            uint32_t b_frag[4][4];
#pragma unroll
            for (int g = 0; g < 4; g++) {
                uint32_t addr = stb + A_BYTES + (uint32_t)((b_r + g * 16) * 128 +
                                (((ks * 2 + b_hi) ^ (b_r & 7)) << 4));
                ldsm4(b_frag[g], addr);
            }
#pragma unroll
            for (int f = 0; f < 2; f++)
#pragma unroll
                for (int g = 0; g < 4; g++) {
                    mma16816(acc[f][2 * g],     a_frag[f], b_frag[g][0], b_frag[g][1]);
                    mma16816(acc[f][2 * g + 1], a_frag[f], b_frag[g][2], b_frag[g][3]);
                }
        }
        __syncthreads();
    }

    // epilogue: direct register -> gmem with fused bias
    const int row0 = bm0 + warp_m * 32 + (lane >> 2);
    const int col0 = bn0 + warp_n * 64 + 2 * (lane & 3);
#pragma unroll
    for (int f = 0; f < 2; f++) {
#pragma unroll
        for (int g = 0; g < 8; g++) {
            const int c = col0 + g * 8;
            const float2 b2 = *reinterpret_cast<const float2*>(bias + c);
            const int r0 = row0 + f * 16;
            float2 v0 = { acc[f][g][0] + b2.x, acc[f][g][1] + b2.y };
            float2 v1 = { acc[f][g][2] + b2.x, acc[f][g][3] + b2.y };
            *reinterpret_cast<float2*>(out + (size_t)r0 * NOUT + c) = v0;
            *reinterpret_cast<float2*>(out + (size_t)(r0 + 8) * NOUT + c) = v1;
        }
    }
}

// ---------------- launch ----------------
extern "C" void kernel_launch(void* const* d_in, const int* in_sizes, int n_in,
                              void* d_out, int out_size) {
    (void)in_sizes; (void)n_in; (void)out_size;
    const float* x    = (const float*)d_in[0];
    const float* w    = (const float*)d_in[1];
    const float* bias = (const float*)d_in[2];
    float* out = (float*)d_out;

    decompose_kernel<<<NOUT, 256>>>(w);
    cvtx_kernel<<<(int)((size_t)NROWS * KIN / 4 / 256), 256>>>(x);

    cudaFuncSetAttribute(gemm_kernel, cudaFuncAttributeMaxDynamicSharedMemorySize, SMEM_TOTAL);
    gemm_kernel<<<dim3(NOUT / BN, NROWS / BM), THREADS, SMEM_TOTAL>>>(bias, out);
}

// round 3
// speedup vs baseline: 1.0582x; 1.0582x over previous
#include <cuda_runtime.h>
#include <cuda_fp16.h>
#include <cstdint>
#include <cstddef>

// Problem dims (fixed by the dataset)
#define KIN   4096
#define NROWS 8192
#define NOUT  4096
#define BASIS 8

// GEMM tiling
#define BM 128
#define BN 256
#define BK 64
#define STAGES 4
#define THREADS 512
#define NKT (KIN / BK)            // 64 k-iterations

#define A_BYTES (BM * BK * 2)     // 16384
#define B_BYTES (BN * BK * 2)     // 32768
#define STG_BYTES (A_BYTES + B_BYTES)        // 49152
#define SMEM_TOTAL (STAGES * STG_BYTES)      // 196608

// prep kernel grid split
#define DEC_BLOCKS 4096
#define CVT_BLOCKS ((NROWS * KIN / 4) / 256)   // 32768
#define PREP_BLOCKS (DEC_BLOCKS + CVT_BLOCKS)

// ---------------- scratch (device globals; no runtime allocation) ----------------
__device__ __half g_w[(size_t)NOUT  * KIN];   // fp16(w_approx), [out, in] K-contiguous
__device__ __half g_x[(size_t)NROWS * KIN];   // fp16(x),        [row, in] K-contiguous

// ---------------- PTX helpers ----------------
__device__ __forceinline__ uint32_t smem_u32(const void* p) {
    uint32_t a;
    asm("{ .reg .u64 t; cvta.to.shared.u64 t, %1; cvt.u32.u64 %0, t; }" : "=r"(a) : "l"(p));
    return a;
}

__device__ __forceinline__ void cp16(uint32_t dst, const void* src) {
    asm volatile("cp.async.cg.shared.global [%0], [%1], 16;" :: "r"(dst), "l"(src));
}
#define CP_COMMIT() asm volatile("cp.async.commit_group;" ::: "memory")

__device__ __forceinline__ void ldsm4(uint32_t (&r)[4], uint32_t addr) {
    asm volatile("ldmatrix.sync.aligned.m8n8.x4.shared.b16 {%0,%1,%2,%3}, [%4];"
                 : "=r"(r[0]), "=r"(r[1]), "=r"(r[2]), "=r"(r[3]) : "r"(addr));
}

__device__ __forceinline__ void mma16816(float (&c)[4], const uint32_t (&a)[4],
                                         uint32_t b0, uint32_t b1) {
    asm volatile(
        "mma.sync.aligned.m16n8k16.row.col.f32.f16.f16.f32 "
        "{%0,%1,%2,%3}, {%4,%5,%6,%7}, {%8,%9}, {%0,%1,%2,%3};"
        : "+f"(c[0]), "+f"(c[1]), "+f"(c[2]), "+f"(c[3])
        : "r"(a[0]), "r"(a[1]), "r"(a[2]), "r"(a[3]), "r"(b0), "r"(b1));
}

// ---------------- Kernel 1: fused prep ----------------
// blocks [0, DEC_BLOCKS): binary decomposition (register-resident residual)
// blocks [DEC_BLOCKS, PREP_BLOCKS): fp32 -> fp16 convert of X
__global__ void __launch_bounds__(256) prep_kernel(const float* __restrict__ W,
                                                   const float* __restrict__ x) {
    const int t = threadIdx.x;

    if (blockIdx.x >= DEC_BLOCKS) {
        // ---- convert X ----
        const size_t i = (size_t)(blockIdx.x - DEC_BLOCKS) * 256 + t;
        float4 v = reinterpret_cast<const float4*>(x)[i];
        __half2* x2 = reinterpret_cast<__half2*>(g_x);
        x2[2 * i + 0] = __halves2half2(__float2half_rn(v.x), __float2half_rn(v.y));
        x2[2 * i + 1] = __halves2half2(__float2half_rn(v.z), __float2half_rn(v.w));
        return;
    }

    // ---- decompose one W row; residual lives in registers ----
    __shared__ float red[8];
    __shared__ float bc;
    const int row = blockIdx.x;
    const int wid = t >> 5, lid = t & 31;
    const float* wr = W + (size_t)row * KIN;

    float wl[16], r[16];
    float s = 0.f;
#pragma unroll
    for (int i = 0; i < 16; i++) { wl[i] = wr[t + 256 * i]; s += wl[i]; }
#pragma unroll
    for (int o = 16; o > 0; o >>= 1) s += __shfl_down_sync(0xffffffffu, s, o);
    if (lid == 0) red[wid] = s;
    __syncthreads();
    if (t == 0) {
        float tot = 0.f;
#pragma unroll
        for (int i = 0; i < 8; i++) tot += red[i];
        bc = tot * (1.f / KIN);
    }
    __syncthreads();
    const float offset = bc;
#pragma unroll
    for (int i = 0; i < 16; i++) r[i] = wl[i] - offset;

#pragma unroll 1
    for (int b = 0; b < BASIS; b++) {
        float a = 0.f;
#pragma unroll
        for (int i = 0; i < 16; i++) a += fabsf(r[i]);
#pragma unroll
        for (int o = 16; o > 0; o >>= 1) a += __shfl_down_sync(0xffffffffu, a, o);
        __syncthreads();                 // protect bc from previous iteration readers
        if (lid == 0) red[wid] = a;
        __syncthreads();
        if (t == 0) {
            float tot = 0.f;
#pragma unroll
            for (int i = 0; i < 8; i++) tot += red[i];
            bc = tot * (1.f / KIN);
        }
        __syncthreads();
        const float c = bc;
#pragma unroll
        for (int i = 0; i < 16; i++) r[i] -= copysignf(c, r[i]);
    }
    // w_approx = w - r_final
    __half* wo = g_w + (size_t)row * KIN;
#pragma unroll
    for (int i = 0; i < 16; i++)
        wo[t + 256 * i] = __float2half_rn(wl[i] - r[i]);
}

// ---------------- Kernel 2: pipelined HMMA GEMM  out = X * W^T + bias ----------------
__global__ void __launch_bounds__(THREADS, 1) gemm_kernel(const float* __restrict__ bias,
                                                          float* __restrict__ out) {
    extern __shared__ char smem[];
    const uint32_t sb = smem_u32(smem);
    const int t = threadIdx.x, wid = t >> 5, lane = t & 31;
    const int bn0 = blockIdx.x * BN;   // N tile
    const int bm0 = blockIdx.y * BM;   // M tile

    const int warp_m = wid & 3;        // 4 M-warps -> 32 rows each
    const int warp_n = wid >> 2;       // 4 N-warps -> 64 cols each

    const __half* a_gsrc = g_x + (size_t)bm0 * KIN;
    const __half* b_gsrc = g_w + (size_t)bn0 * KIN;

    int a_row[2], a_kc[2];
    uint32_t a_dst[2];
#pragma unroll
    for (int i = 0; i < 2; i++) {
        int c = t + THREADS * i;
        a_row[i] = c >> 3; a_kc[i] = c & 7;
        a_dst[i] = (uint32_t)(a_row[i] * 128 + ((a_kc[i] ^ (a_row[i] & 7)) << 4));
    }
    int b_row[4], b_kc[4];
    uint32_t b_dst[4];
#pragma unroll
    for (int i = 0; i < 4; i++) {
        int c = t + THREADS * i;
        b_row[i] = c >> 3; b_kc[i] = c & 7;
        b_dst[i] = (uint32_t)(b_row[i] * 128 + ((b_kc[i] ^ (b_row[i] & 7)) << 4)) + A_BYTES;
    }

    auto load_stage = [&](int kt, int s) {
        const uint32_t stb = sb + (uint32_t)s * STG_BYTES;
        const int k0 = kt * BK;
#pragma unroll
        for (int i = 0; i < 2; i++)
            cp16(stb + a_dst[i], a_gsrc + (size_t)a_row[i] * KIN + k0 + a_kc[i] * 8);
#pragma unroll
        for (int i = 0; i < 4; i++)
            cp16(stb + b_dst[i], b_gsrc + (size_t)b_row[i] * KIN + k0 + b_kc[i] * 8);
        CP_COMMIT();
    };

    // ldmatrix lane coordinates
    const int a_r  = warp_m * 32 + (lane & 7) + ((lane >> 3) & 1) * 8;  // + f*16
    const int a_hi = (lane >> 4) & 1;
    const int b_r  = warp_n * 64 + (lane & 7) + ((lane >> 4) & 1) * 8;   // + g*16
    const int b_hi = (lane >> 3) & 1;

    float acc[2][8][4];
#pragma unroll
    for (int f = 0; f < 2; f++)
#pragma unroll
        for (int g = 0; g < 8; g++)
#pragma unroll
            for (int q = 0; q < 4; q++) acc[f][g][q] = 0.f;

    // prologue: stages 0..STAGES-2
#pragma unroll
    for (int s = 0; s < STAGES - 1; s++) load_stage(s, s);

    for (int kt = 0; kt < NKT; ++kt) {
        asm volatile("cp.async.wait_group %0;" :: "n"(STAGES - 2) : "memory");
        // Single barrier per iteration: passing it means every warp finished
        // iteration kt-1's ldsm reads, so overwriting slot (kt+3)%4 == (kt-1)%4
        // below is safe, and stage kt%4's cp.async data is visible to all.
        __syncthreads();

        const int pf = kt + STAGES - 1;
        if (pf < NKT) load_stage(pf, pf % STAGES);
        else          CP_COMMIT();       // empty group keeps wait accounting correct

        const uint32_t stb = sb + (uint32_t)(kt % STAGES) * STG_BYTES;
#pragma unroll
        for (int ks = 0; ks < 4; ks++) {
            uint32_t a_frag[2][4];
#pragma unroll
            for (int f = 0; f < 2; f++) {
                uint32_t addr = stb + (uint32_t)((a_r + f * 16) * 128 +
                                (((ks * 2 + a_hi) ^ (a_r & 7)) << 4));
                ldsm4(a_frag[f], addr);
            }
            uint32_t b_frag[4][4];
#pragma unroll
            for (int g = 0; g < 4; g++) {
                uint32_t addr = stb + A_BYTES + (uint32_t)((b_r + g * 16) * 128 +
                                (((ks * 2 + b_hi) ^ (b_r & 7)) << 4));
                ldsm4(b_frag[g], addr);
            }
#pragma unroll
            for (int f = 0; f < 2; f++)
#pragma unroll
                for (int g = 0; g < 4; g++) {
                    mma16816(acc[f][2 * g],     a_frag[f], b_frag[g][0], b_frag[g][1]);
                    mma16816(acc[f][2 * g + 1], a_frag[f], b_frag[g][2], b_frag[g][3]);
                }
        }
    }

    // epilogue: direct register -> gmem with fused bias
    const int row0 = bm0 + warp_m * 32 + (lane >> 2);
    const int col0 = bn0 + warp_n * 64 + 2 * (lane & 3);
#pragma unroll
    for (int f = 0; f < 2; f++) {
#pragma unroll
        for (int g = 0; g < 8; g++) {
            const int c = col0 + g * 8;
            const float2 b2 = *reinterpret_cast<const float2*>(bias + c);
            const int r0 = row0 + f * 16;
            float2 v0 = { acc[f][g][0] + b2.x, acc[f][g][1] + b2.y };
            float2 v1 = { acc[f][g][2] + b2.x, acc[f][g][3] + b2.y };
            *reinterpret_cast<float2*>(out + (size_t)r0 * NOUT + c) = v0;
            *reinterpret_cast<float2*>(out + (size_t)(r0 + 8) * NOUT + c) = v1;
        }
    }
}

// ---------------- launch ----------------
extern "C" void kernel_launch(void* const* d_in, const int* in_sizes, int n_in,
                              void* d_out, int out_size) {
    (void)in_sizes; (void)n_in; (void)out_size;
    const float* x    = (const float*)d_in[0];
    const float* w    = (const float*)d_in[1];
    const float* bias = (const float*)d_in[2];
    float* out = (float*)d_out;

    prep_kernel<<<PREP_BLOCKS, 256>>>(w, x);

    cudaFuncSetAttribute(gemm_kernel, cudaFuncAttributeMaxDynamicSharedMemorySize, SMEM_TOTAL);
    gemm_kernel<<<dim3(NOUT / BN, NROWS / BM), THREADS, SMEM_TOTAL>>>(bias, out);
}